// round 7
// baseline (speedup 1.0000x reference)
#include <cuda_runtime.h>
#include <math.h>
#include <stdint.h>

typedef unsigned long long ull;

#define NB 32
#define NT 1000
#define ND 512
#define TT1 1001

// d_out layout: acoustic [32,1001,512] | token_num [32] | alphas_t [32,1001] | cif_peak [32,1001] | token_num2 [32]
#define N_AC   (NB*TT1*ND)
#define OFF_TN (N_AC)
#define OFF_AT (OFF_TN + NB)
#define OFF_CP (OFF_AT + NB*TT1)
#define OFF_TN2 (OFF_CP + NB*TT1)

// ---------------- scratch ----------------
__device__ __align__(1024) float g_Wt[3*ND*ND];   // conv weights [k][i][o]
__device__ __align__(1024) float g_dotp[NB*NT*6*8]; // partial dots [b*NT+t][q][oslice]
__device__ float g_v[5*ND];
__device__ float g_c2;
__device__ float g_a2sum[NB*NT];
__device__ float g_coeff[NB*TT1];
__device__ int   g_firepos[NB*TT1];
__device__ int   g_ntok[NB];

__device__ __forceinline__ void ffma2(ull &d, ull a, ull b) {
    asm("fma.rn.f32x2 %0, %1, %2, %0;" : "+l"(d) : "l"(a), "l"(b));
}
__device__ __forceinline__ ull dupf(float v) {
    ull d;
    asm("mov.b64 %0, {%1, %1};" : "=l"(d) : "f"(v));
    return d;
}
__device__ __forceinline__ uint32_t smem_u32(const void* p) {
    uint32_t a;
    asm("{ .reg .u64 t; cvta.to.shared.u64 t, %1; cvt.u32.u64 %0, t; }" : "=r"(a) : "l"(p));
    return a;
}
__device__ __forceinline__ void cp16(uint32_t dst, const void* src) {
    asm volatile("cp.async.cg.shared.global [%0], [%1], 16;" :: "r"(dst), "l"(src) : "memory");
}
__device__ __forceinline__ float sigmoidf_acc(float x) {
    if (x >= 0.f) { float z = expf(-x); return 1.f / (1.f + z); }
    float z = expf(x); return z / (1.f + z);
}

// ---------------- prep kernels ----------------
__global__ void k_prep_wt(const float* __restrict__ cw) {
    int idx = blockIdx.x * blockDim.x + threadIdx.x;
    if (idx < 3*ND*ND) {
        int o = idx & 511;
        int i = (idx >> 9) & 511;
        int k = idx >> 18;
        g_Wt[idx] = cw[(o*ND + i)*3 + k];
    }
}

// blocks 0..511: v rows; block 512: c2
__global__ void k_prep_vc(const float* __restrict__ uw, const float* __restrict__ w2,
                          const float* __restrict__ ub, const float* __restrict__ b2) {
    int i = blockIdx.x;
    if (i < ND) {
        int j = threadIdx.x >> 5, lane = threadIdx.x & 31;
        float s = 0.f;
        for (int o = lane; o < ND; o += 32) s += uw[((size_t)i*ND + o)*5 + j] * w2[o];
        #pragma unroll
        for (int o = 16; o > 0; o >>= 1) s += __shfl_xor_sync(0xffffffffu, s, o);
        if (lane == 0) g_v[j*ND + i] = s;
    } else if (threadIdx.x < 32) {
        int lane = threadIdx.x;
        float s = 0.f;
        for (int o = lane; o < ND; o += 32) s += ub[o] * w2[o];
        #pragma unroll
        for (int o = 16; o > 0; o >>= 1) s += __shfl_xor_sync(0xffffffffu, s, o);
        if (lane == 0) g_c2 = s + b2[0];
    }
}

// ---------------- K1: FFMA2 conv GEMM + fused projection epilogue ----------------
// C[t,o] = relu( sum_{k,i} enc[b, t+k-1, i] * Wt[k][i][o] + conv_b[o] )
// CTA: 256 thr, tile 128t x 128o, BK=16, 32 chunks, 2-stage pipeline.
// warp layout: tx = (wid&1)*8 + (lane&7), ty = (wid>>1)*4 + (lane>>3)  -> warp = 32t x 64o
// stage: Asp [16][132] float packed 8448B + Bs [3][16][128] float 24576B = 33024B
#define A_BYTES 8448
#define STAGE_BYTES 33024
#define SMEM_CONV (2*STAGE_BYTES)

__global__ void __launch_bounds__(256, 2) k_conv_gemm(const float* __restrict__ enc,
                                                      const float* __restrict__ cb,
                                                      const float* __restrict__ w1) {
    extern __shared__ __align__(16) char dsm[];
    const int b  = blockIdx.z;
    const int t0 = blockIdx.x * 128;
    const int o0 = blockIdx.y * 128;
    const int tid = threadIdx.x;
    const int wid = tid >> 5, lane = tid & 31;
    const int tx = (wid & 1) * 8 + (lane & 7);     // o direction (0..15)
    const int ty = (wid >> 1) * 4 + (lane >> 3);   // t direction (0..15)

    const uint32_t smem = smem_u32(dsm);

    ull acc[8][4];
    #pragma unroll
    for (int m = 0; m < 8; ++m)
        #pragma unroll
        for (int n = 0; n < 4; ++n) acc[m][n] = 0ull;

    auto ldgA = [&](int i0, float4* vbuf) {
        #pragma unroll
        for (int p = 0; p < 3; ++p) {
            int idx = tid + p*256;
            vbuf[p] = make_float4(0.f, 0.f, 0.f, 0.f);
            if (idx < 520) {
                int r = idx >> 2, c4 = idx & 3;
                int t = t0 - 1 + r;
                if (t >= 0 && t < NT)
                    vbuf[p] = *(const float4*)(enc + ((size_t)b*NT + t)*ND + i0 + c4*4);
            }
        }
    };
    auto stsA = [&](int s, const float4* vbuf) {
        float* Asp = (float*)(dsm + s*STAGE_BYTES);
        #pragma unroll
        for (int p = 0; p < 3; ++p) {
            int idx = tid + p*256;
            if (idx < 520) {
                int r = idx >> 2, c4 = idx & 3;
                float4 val = vbuf[p];
                Asp[(c4*4+0)*132 + r] = val.x;
                Asp[(c4*4+1)*132 + r] = val.y;
                Asp[(c4*4+2)*132 + r] = val.z;
                Asp[(c4*4+3)*132 + r] = val.w;
            }
        }
    };
    auto cpB = [&](int s, int i0) {
        uint32_t Bs = smem + s*STAGE_BYTES + A_BYTES;
        #pragma unroll
        for (int p = 0; p < 6; ++p) {
            int idx = tid + p*256;            // < 1536
            int kk = idx >> 9;
            int ii = (idx >> 5) & 15;
            int c4 = idx & 31;
            cp16(Bs + (uint32_t)(((kk*16 + ii)*128 + c4*4)*4),
                 g_Wt + ((size_t)kk*ND + i0 + ii)*ND + o0 + c4*4);
        }
        asm volatile("cp.async.commit_group;" ::: "memory");
    };

    float4 vbuf[3];
    ldgA(0, vbuf);  stsA(0, vbuf);  cpB(0, 0);
    ldgA(16, vbuf); stsA(1, vbuf);  cpB(1, 16);

    for (int c = 0; c < 32; ++c) {
        const int s = c & 1;
        if (c < 30) asm volatile("cp.async.wait_group 1;" ::: "memory");
        else        asm volatile("cp.async.wait_group 0;" ::: "memory");
        __syncthreads();

        if (c < 30) ldgA((c + 2) * 16, vbuf);

        const float* Asp = (const float*)(dsm + s*STAGE_BYTES);
        const float* Bsf = (const float*)(dsm + s*STAGE_BYTES + A_BYTES);
        #pragma unroll
        for (int ii = 0; ii < 16; ++ii) {
            const float4* ap = (const float4*)(Asp + ii*132 + ty*8);
            ull a[10];
            {
                float4 p0 = ap[0];
                a[0] = dupf(p0.x); a[1] = dupf(p0.y); a[2] = dupf(p0.z); a[3] = dupf(p0.w);
                float4 p1 = ap[1];
                a[4] = dupf(p1.x); a[5] = dupf(p1.y); a[6] = dupf(p1.z); a[7] = dupf(p1.w);
                float2 p2 = *(const float2*)(Asp + ii*132 + ty*8 + 8);
                a[8] = dupf(p2.x); a[9] = dupf(p2.y);
            }
            #pragma unroll
            for (int k = 0; k < 3; ++k) {
                const ulonglong2* bp = (const ulonglong2*)(Bsf + (k*16 + ii)*128 + tx*8);
                ulonglong2 b01 = bp[0];
                ulonglong2 b23 = bp[1];
                #pragma unroll
                for (int m = 0; m < 8; ++m) {
                    ffma2(acc[m][0], a[m+k], b01.x);
                    ffma2(acc[m][1], a[m+k], b01.y);
                    ffma2(acc[m][2], a[m+k], b23.x);
                    ffma2(acc[m][3], a[m+k], b23.y);
                }
            }
        }
        __syncthreads();

        if (c < 30) { stsA(s, vbuf); cpB(s, (c + 2) * 16); }
    }

    // ---- fused epilogue: bias+relu, 6 dot partials per t-row, 8-lane reduce, store ----
    const int obase = o0 + tx*8;
    float bias[8];
    #pragma unroll
    for (int j = 0; j < 8; ++j) bias[j] = cb[obase + j];

    float wv[6][8];
    #pragma unroll
    for (int h = 0; h < 8; h += 4) {
        float4 wq = *(const float4*)(w1 + obase + h);
        wv[0][h] = wq.x; wv[0][h+1] = wq.y; wv[0][h+2] = wq.z; wv[0][h+3] = wq.w;
        #pragma unroll
        for (int j = 0; j < 5; ++j) {
            float4 vq = *(const float4*)(g_v + j*ND + obase + h);
            wv[1+j][h] = vq.x; wv[1+j][h+1] = vq.y; wv[1+j][h+2] = vq.z; wv[1+j][h+3] = vq.w;
        }
    }

    const int oslice = blockIdx.y * 2 + (wid & 1);   // 8 slices of 64 o
    #pragma unroll
    for (int m = 0; m < 8; ++m) {
        int t = t0 + ty*8 + m;
        float outv[8];
        #pragma unroll
        for (int n = 0; n < 4; ++n) {
            float lo = __uint_as_float((unsigned)(acc[m][n] & 0xffffffffull));
            float hi = __uint_as_float((unsigned)(acc[m][n] >> 32));
            outv[2*n]   = fmaxf(lo + bias[2*n],   0.f);
            outv[2*n+1] = fmaxf(hi + bias[2*n+1], 0.f);
        }
        float p[6];
        #pragma unroll
        for (int q = 0; q < 6; ++q) {
            float s = 0.f;
            #pragma unroll
            for (int j = 0; j < 8; ++j) s = fmaf(outv[j], wv[q][j], s);
            #pragma unroll
            for (int o = 1; o < 8; o <<= 1) s += __shfl_xor_sync(0xffffffffu, s, o);
            p[q] = s;
        }
        if ((lane & 7) == 0 && t < NT) {
            float* dp = g_dotp + ((size_t)(b*NT + t))*48 + oslice;
            #pragma unroll
            for (int q = 0; q < 6; ++q) dp[q*8] = p[q];
        }
    }
}

// ---------------- K2: combine dot partials -> alphas_t[t<T], a2sum ----------------
__global__ void __launch_bounds__(256) k_alpha(const float* __restrict__ mask,
        const float* __restrict__ b1, float* __restrict__ out_at) {
    int m = blockIdx.x * 256 + threadIdx.x;
    if (m >= NB*NT) return;
    int b = m / NT, t = m - b*NT;
    const float* dp = g_dotp + (size_t)m*48;
    float s[6];
    #pragma unroll
    for (int q = 0; q < 6; ++q) {
        const float* d = dp + q*8;
        s[q] = ((d[0] + d[1]) + (d[2] + d[3])) + ((d[4] + d[5]) + (d[6] + d[7]));
    }
    float mv = mask[b*NT + t];
    float alpha = fmaxf(sigmoidf_acc(s[0] + b1[0]), 0.f) * mv;
    float m2 = (t == 0) ? 1.f : mask[b*NT + t - 1];
    out_at[b*TT1 + t] = alpha + (m2 - mv) * 0.45f;
    float c2 = g_c2;
    float s2 = 0.f;
    #pragma unroll
    for (int j = 0; j < 5; ++j) s2 += fmaxf(sigmoidf_acc(s[1+j] + c2), 0.f);
    g_a2sum[m] = s2 * mv;
}

// ---------------- K3: scalar CIF scan per batch ----------------
__global__ void k_scan(const float* __restrict__ mask, float* __restrict__ out) {
    int b = blockIdx.x, lane = threadIdx.x;
    float* out_at = out + OFF_AT;
    float* out_cp = out + OFF_CP;

    double s2 = 0.0;
    for (int t = lane; t < NT; t += 32) s2 += (double)g_a2sum[b*NT + t];
    #pragma unroll
    for (int o = 16; o > 0; o >>= 1) s2 += __shfl_xor_sync(0xffffffffu, s2, o);
    if (lane == 0) out[OFF_TN2 + b] = (float)s2;

    float tailv = mask[b*NT + NT - 1] * 0.45f;
    if (lane == 0) out_at[b*TT1 + NT] = tailv;

    float integ = 0.f; double asum = 0.0; int ntok = 0;
    for (int c = 0; c < TT1; c += 32) {
        int t = c + lane;
        float av = 0.f;
        if (t < NT) av = out_at[b*TT1 + t];
        else if (t == NT) av = tailv;
        float my_peak = 0.f, my_coeff = 0.f;
        int lim = TT1 - c; if (lim > 32) lim = 32;
        for (int s = 0; s < lim; ++s) {
            float alpha = __shfl_sync(0xffffffffu, av, s);
            asum += (double)alpha;
            float dist = 1.f - integ;
            integ += alpha;
            float fires = integ;
            float cur = alpha;
            if (fires >= 1.f) {
                integ -= 1.f;
                cur = dist;
                if (lane == 0) g_firepos[b*TT1 + ntok] = c + s;
                ntok++;
            }
            if (lane == s) { my_peak = fires; my_coeff = cur; }
        }
        if (t < TT1) { out_cp[b*TT1 + t] = my_peak; g_coeff[b*TT1 + t] = my_coeff; }
    }
    if (lane == 0) { out[OFF_TN + b] = floorf((float)asum); g_ntok[b] = ntok; }
}

// ---------------- K4: parallel token gather-sum ----------------
__global__ void __launch_bounds__(128) k_gather(const float* __restrict__ enc,
                                                float* __restrict__ out) {
    int b = blockIdx.y, n = blockIdx.x, tid = threadIdx.x;
    const float* at = out + OFF_AT;
    float4 acc = make_float4(0.f,0.f,0.f,0.f);
    if (n < g_ntok[b]) {
        int te = g_firepos[b*TT1 + n];
        int tstart = 0;
        if (n > 0) {
            int tp = g_firepos[b*TT1 + n - 1];
            float lw = at[b*TT1 + tp] - g_coeff[b*TT1 + tp];
            if (tp < NT) {
                float4 h = *(const float4*)(enc + ((size_t)b*NT + tp)*ND + tid*4);
                acc.x = lw*h.x; acc.y = lw*h.y; acc.z = lw*h.z; acc.w = lw*h.w;
            }
            tstart = tp + 1;
        }
        for (int t = tstart; t <= te; ++t) {
            if (t >= NT) break;
            float cf = g_coeff[b*TT1 + t];
            float4 h = *(const float4*)(enc + ((size_t)b*NT + t)*ND + tid*4);
            acc.x = fmaf(cf, h.x, acc.x);
            acc.y = fmaf(cf, h.y, acc.y);
            acc.z = fmaf(cf, h.z, acc.z);
            acc.w = fmaf(cf, h.w, acc.w);
        }
    }
    *(float4*)(out + ((size_t)(b*TT1 + n))*ND + tid*4) = acc;
}

// ---------------- launch ----------------
extern "C" void kernel_launch(void* const* d_in, const int* in_sizes, int n_in,
                              void* d_out, int out_size) {
    (void)in_sizes; (void)n_in; (void)out_size;
    const float* enc  = (const float*)d_in[0];
    const float* mask = (const float*)d_in[1];
    const float* cw   = (const float*)d_in[2];
    const float* cb   = (const float*)d_in[3];
    const float* uw   = (const float*)d_in[4];
    const float* ub   = (const float*)d_in[5];
    const float* w1   = (const float*)d_in[6];
    const float* b1   = (const float*)d_in[7];
    const float* w2   = (const float*)d_in[8];
    const float* b2   = (const float*)d_in[9];
    float* out = (float*)d_out;

    cudaFuncSetAttribute(k_conv_gemm, cudaFuncAttributeMaxDynamicSharedMemorySize, SMEM_CONV);

    k_prep_wt<<<(3*ND*ND + 255)/256, 256>>>(cw);
    k_prep_vc<<<ND + 1, 160>>>(uw, w2, ub, b2);

    dim3 g1(8, 4, NB);               // t-tiles x o-tiles x batch
    k_conv_gemm<<<g1, 256, SMEM_CONV>>>(enc, cb, w1);

    k_alpha<<<(NB*NT + 255)/256, 256>>>(mask, b1, out + OFF_AT);
    k_scan<<<NB, 32>>>(mask, out);

    dim3 g4(TT1, NB);
    k_gather<<<g4, 128>>>(enc, out);
}

// round 8
// speedup vs baseline: 1.0104x; 1.0104x over previous
#include <cuda_runtime.h>
#include <math.h>
#include <stdint.h>

typedef unsigned long long ull;

#define NB 32
#define NT 1000
#define ND 512
#define TT1 1001

// d_out layout: acoustic [32,1001,512] | token_num [32] | alphas_t [32,1001] | cif_peak [32,1001] | token_num2 [32]
#define N_AC   (NB*TT1*ND)
#define OFF_TN (N_AC)
#define OFF_AT (OFF_TN + NB)
#define OFF_CP (OFF_AT + NB*TT1)
#define OFF_TN2 (OFF_CP + NB*TT1)

// ---------------- scratch ----------------
__device__ __align__(1024) float g_Wt[3*ND*ND];     // conv weights [k][i][o]
__device__ __align__(1024) float g_dotp[NB*NT*6*4]; // partial dots [b*NT+t][q][oslice 0..3]
__device__ float g_v[5*ND];
__device__ float g_c2;
__device__ float g_a2sum[NB*NT];
__device__ float g_coeff[NB*TT1];
__device__ int   g_firepos[NB*TT1];
__device__ int   g_ntok[NB];

__device__ __forceinline__ void ffma2(ull &d, ull a, ull b) {
    asm("fma.rn.f32x2 %0, %1, %2, %0;" : "+l"(d) : "l"(a), "l"(b));
}
__device__ __forceinline__ ull dupf(float v) {
    ull d;
    asm("mov.b64 %0, {%1, %1};" : "=l"(d) : "f"(v));
    return d;
}
__device__ __forceinline__ uint32_t smem_u32(const void* p) {
    uint32_t a;
    asm("{ .reg .u64 t; cvta.to.shared.u64 t, %1; cvt.u32.u64 %0, t; }" : "=r"(a) : "l"(p));
    return a;
}
__device__ __forceinline__ void cp16(uint32_t dst, const void* src) {
    asm volatile("cp.async.cg.shared.global [%0], [%1], 16;" :: "r"(dst), "l"(src) : "memory");
}
__device__ __forceinline__ float sigmoidf_acc(float x) {
    if (x >= 0.f) { float z = expf(-x); return 1.f / (1.f + z); }
    float z = expf(x); return z / (1.f + z);
}

// ---------------- prep kernels ----------------
__global__ void k_prep_wt(const float* __restrict__ cw) {
    int idx = blockIdx.x * blockDim.x + threadIdx.x;
    if (idx < 3*ND*ND) {
        int o = idx & 511;
        int i = (idx >> 9) & 511;
        int k = idx >> 18;
        g_Wt[idx] = cw[(o*ND + i)*3 + k];
    }
}

// blocks 0..511: v rows; block 512: c2
__global__ void k_prep_vc(const float* __restrict__ uw, const float* __restrict__ w2,
                          const float* __restrict__ ub, const float* __restrict__ b2) {
    int i = blockIdx.x;
    if (i < ND) {
        int j = threadIdx.x >> 5, lane = threadIdx.x & 31;
        float s = 0.f;
        for (int o = lane; o < ND; o += 32) s += uw[((size_t)i*ND + o)*5 + j] * w2[o];
        #pragma unroll
        for (int o = 16; o > 0; o >>= 1) s += __shfl_xor_sync(0xffffffffu, s, o);
        if (lane == 0) g_v[j*ND + i] = s;
    } else if (threadIdx.x < 32) {
        int lane = threadIdx.x;
        float s = 0.f;
        for (int o = lane; o < ND; o += 32) s += ub[o] * w2[o];
        #pragma unroll
        for (int o = 16; o > 0; o >>= 1) s += __shfl_xor_sync(0xffffffffu, s, o);
        if (lane == 0) g_c2 = s + b2[0];
    }
}

// ---------------- K1: FFMA2 conv GEMM (R6 layout) + register-neutral fused epilogue ----------------
// C[t,o] = relu( sum_{k,i} enc[b, t+k-1, i] * Wt[k][i][o] + conv_b[o] )
// CTA: 256 thr (tx=tid&15 over o, ty=tid>>4 over t), tile 128x128, BK=16, 2-stage pipeline.
// stage: Asp [16][132] float packed 8448B + Bs [3][16][128] float 24576B = 33024B
// + 3KB weight stage (w1,v0..v4 for this o-block) at offset 2*STAGE_BYTES.
#define A_BYTES 8448
#define STAGE_BYTES 33024
#define W_OFF   (2*STAGE_BYTES)
#define SMEM_CONV (2*STAGE_BYTES + 6*128*4)

__global__ void __launch_bounds__(256, 2) k_conv_gemm(const float* __restrict__ enc,
                                                      const float* __restrict__ cb,
                                                      const float* __restrict__ w1) {
    extern __shared__ __align__(16) char dsm[];
    const int b  = blockIdx.z;
    const int t0 = blockIdx.x * 128;
    const int o0 = blockIdx.y * 128;
    const int tid = threadIdx.x;
    const int tx = tid & 15;     // o direction
    const int ty = tid >> 4;     // t direction

    const uint32_t smem = smem_u32(dsm);

    // stage the 6 projection vectors for this o-block into smem (one-time)
    {
        float* wsm = (float*)(dsm + W_OFF);
        if (tid < 128) wsm[tid] = w1[o0 + tid];
        else if (tid < 224) {
            int j = (tid - 128) / 16;          // 0..5 -> rows of g_v via 16-thr groups? simpler below
        }
        // 5 v rows, 128 each: threads 0..255 cover 640 with 3 strided passes
        for (int idx = tid; idx < 5*128; idx += 256)
            wsm[128 + idx] = g_v[(idx >> 7) * ND + o0 + (idx & 127)];
    }

    ull acc[8][4];
    #pragma unroll
    for (int m = 0; m < 8; ++m)
        #pragma unroll
        for (int n = 0; n < 4; ++n) acc[m][n] = 0ull;

    auto ldgA = [&](int i0, float4* vbuf) {
        #pragma unroll
        for (int p = 0; p < 3; ++p) {
            int idx = tid + p*256;
            vbuf[p] = make_float4(0.f, 0.f, 0.f, 0.f);
            if (idx < 520) {
                int r = idx >> 2, c4 = idx & 3;
                int t = t0 - 1 + r;
                if (t >= 0 && t < NT)
                    vbuf[p] = *(const float4*)(enc + ((size_t)b*NT + t)*ND + i0 + c4*4);
            }
        }
    };
    auto stsA = [&](int s, const float4* vbuf) {
        float* Asp = (float*)(dsm + s*STAGE_BYTES);
        #pragma unroll
        for (int p = 0; p < 3; ++p) {
            int idx = tid + p*256;
            if (idx < 520) {
                int r = idx >> 2, c4 = idx & 3;
                float4 val = vbuf[p];
                Asp[(c4*4+0)*132 + r] = val.x;
                Asp[(c4*4+1)*132 + r] = val.y;
                Asp[(c4*4+2)*132 + r] = val.z;
                Asp[(c4*4+3)*132 + r] = val.w;
            }
        }
    };
    auto cpB = [&](int s, int i0) {
        uint32_t Bs = smem + s*STAGE_BYTES + A_BYTES;
        #pragma unroll
        for (int p = 0; p < 6; ++p) {
            int idx = tid + p*256;            // < 1536
            int kk = idx >> 9;
            int ii = (idx >> 5) & 15;
            int c4 = idx & 31;
            cp16(Bs + (uint32_t)(((kk*16 + ii)*128 + c4*4)*4),
                 g_Wt + ((size_t)kk*ND + i0 + ii)*ND + o0 + c4*4);
        }
        asm volatile("cp.async.commit_group;" ::: "memory");
    };

    float4 vbuf[3];
    ldgA(0, vbuf);  stsA(0, vbuf);  cpB(0, 0);
    ldgA(16, vbuf); stsA(1, vbuf);  cpB(1, 16);

    for (int c = 0; c < 32; ++c) {
        const int s = c & 1;
        if (c < 30) asm volatile("cp.async.wait_group 1;" ::: "memory");
        else        asm volatile("cp.async.wait_group 0;" ::: "memory");
        __syncthreads();

        if (c < 30) ldgA((c + 2) * 16, vbuf);

        const float* Asp = (const float*)(dsm + s*STAGE_BYTES);
        const float* Bsf = (const float*)(dsm + s*STAGE_BYTES + A_BYTES);
        #pragma unroll
        for (int ii = 0; ii < 16; ++ii) {
            const float4* ap = (const float4*)(Asp + ii*132 + ty*8);
            ull a[10];
            {
                float4 p0 = ap[0];
                a[0] = dupf(p0.x); a[1] = dupf(p0.y); a[2] = dupf(p0.z); a[3] = dupf(p0.w);
                float4 p1 = ap[1];
                a[4] = dupf(p1.x); a[5] = dupf(p1.y); a[6] = dupf(p1.z); a[7] = dupf(p1.w);
                float2 p2 = *(const float2*)(Asp + ii*132 + ty*8 + 8);
                a[8] = dupf(p2.x); a[9] = dupf(p2.y);
            }
            #pragma unroll
            for (int k = 0; k < 3; ++k) {
                const ulonglong2* bp = (const ulonglong2*)(Bsf + (k*16 + ii)*128 + tx*8);
                ulonglong2 b01 = bp[0];
                ulonglong2 b23 = bp[1];
                #pragma unroll
                for (int m = 0; m < 8; ++m) {
                    ffma2(acc[m][0], a[m+k], b01.x);
                    ffma2(acc[m][1], a[m+k], b01.y);
                    ffma2(acc[m][2], a[m+k], b23.x);
                    ffma2(acc[m][3], a[m+k], b23.y);
                }
            }
        }
        __syncthreads();

        if (c < 30) { stsA(s, vbuf); cpB(s, (c + 2) * 16); }
    }

    // ---- fused epilogue: in-place bias+relu, 6 smem-weight dots, 16-lane reduce ----
    float bias[8];
    #pragma unroll
    for (int j = 0; j < 8; ++j) bias[j] = cb[o0 + tx*8 + j];

    float* accf = reinterpret_cast<float*>(acc);   // accf[(m*4+n)*2 + {0,1}]
    #pragma unroll
    for (int m = 0; m < 8; ++m)
        #pragma unroll
        for (int n = 0; n < 4; ++n) {
            float lo = accf[(m*4+n)*2],  hi = accf[(m*4+n)*2 + 1];
            accf[(m*4+n)*2]     = fmaxf(lo + bias[2*n],   0.f);
            accf[(m*4+n)*2 + 1] = fmaxf(hi + bias[2*n+1], 0.f);
        }

    const float* wsm = (const float*)(dsm + W_OFF);
    const int lane = tid & 31;
    const int tbase = t0 + ty*8;
    #pragma unroll
    for (int q = 0; q < 6; ++q) {
        float wq[8];
        *(float4*)(wq)     = *(const float4*)(wsm + q*128 + tx*8);
        *(float4*)(wq + 4) = *(const float4*)(wsm + q*128 + tx*8 + 4);
        #pragma unroll
        for (int m = 0; m < 8; ++m) {
            float s = 0.f;
            #pragma unroll
            for (int j = 0; j < 8; ++j) s = fmaf(accf[m*8 + j], wq[j], s);
            #pragma unroll
            for (int o = 1; o < 16; o <<= 1) s += __shfl_xor_sync(0xffffffffu, s, o);
            int t = tbase + m;
            if ((lane & 15) == 0 && t < NT)
                g_dotp[((size_t)(b*NT + t)*6 + q)*4 + blockIdx.y] = s;
        }
    }
}

// ---------------- K2: combine dot partials -> alphas_t[t<T], a2sum ----------------
__global__ void __launch_bounds__(256) k_alpha(const float* __restrict__ mask,
        const float* __restrict__ b1, float* __restrict__ out_at) {
    int m = blockIdx.x * 256 + threadIdx.x;
    if (m >= NB*NT) return;
    int b = m / NT, t = m - b*NT;
    const float* dp = g_dotp + (size_t)m*24;
    float s[6];
    #pragma unroll
    for (int q = 0; q < 6; ++q) {
        const float* d = dp + q*4;
        s[q] = (d[0] + d[1]) + (d[2] + d[3]);
    }
    float mv = mask[b*NT + t];
    float alpha = fmaxf(sigmoidf_acc(s[0] + b1[0]), 0.f) * mv;
    float m2 = (t == 0) ? 1.f : mask[b*NT + t - 1];
    out_at[b*TT1 + t] = alpha + (m2 - mv) * 0.45f;
    float c2 = g_c2;
    float s2 = 0.f;
    #pragma unroll
    for (int j = 0; j < 5; ++j) s2 += fmaxf(sigmoidf_acc(s[1+j] + c2), 0.f);
    g_a2sum[m] = s2 * mv;
}

// ---------------- K3: scalar CIF scan per batch ----------------
__global__ void k_scan(const float* __restrict__ mask, float* __restrict__ out) {
    int b = blockIdx.x, lane = threadIdx.x;
    float* out_at = out + OFF_AT;
    float* out_cp = out + OFF_CP;

    double s2 = 0.0;
    for (int t = lane; t < NT; t += 32) s2 += (double)g_a2sum[b*NT + t];
    #pragma unroll
    for (int o = 16; o > 0; o >>= 1) s2 += __shfl_xor_sync(0xffffffffu, s2, o);
    if (lane == 0) out[OFF_TN2 + b] = (float)s2;

    float tailv = mask[b*NT + NT - 1] * 0.45f;
    if (lane == 0) out_at[b*TT1 + NT] = tailv;

    float integ = 0.f; double asum = 0.0; int ntok = 0;
    for (int c = 0; c < TT1; c += 32) {
        int t = c + lane;
        float av = 0.f;
        if (t < NT) av = out_at[b*TT1 + t];
        else if (t == NT) av = tailv;
        float my_peak = 0.f, my_coeff = 0.f;
        int lim = TT1 - c; if (lim > 32) lim = 32;
        for (int s = 0; s < lim; ++s) {
            float alpha = __shfl_sync(0xffffffffu, av, s);
            asum += (double)alpha;
            float dist = 1.f - integ;
            integ += alpha;
            float fires = integ;
            float cur = alpha;
            if (fires >= 1.f) {
                integ -= 1.f;
                cur = dist;
                if (lane == 0) g_firepos[b*TT1 + ntok] = c + s;
                ntok++;
            }
            if (lane == s) { my_peak = fires; my_coeff = cur; }
        }
        if (t < TT1) { out_cp[b*TT1 + t] = my_peak; g_coeff[b*TT1 + t] = my_coeff; }
    }
    if (lane == 0) { out[OFF_TN + b] = floorf((float)asum); g_ntok[b] = ntok; }
}

// ---------------- K4: parallel token gather-sum ----------------
__global__ void __launch_bounds__(128) k_gather(const float* __restrict__ enc,
                                                float* __restrict__ out) {
    int b = blockIdx.y, n = blockIdx.x, tid = threadIdx.x;
    const float* at = out + OFF_AT;
    float4 acc = make_float4(0.f,0.f,0.f,0.f);
    if (n < g_ntok[b]) {
        int te = g_firepos[b*TT1 + n];
        int tstart = 0;
        if (n > 0) {
            int tp = g_firepos[b*TT1 + n - 1];
            float lw = at[b*TT1 + tp] - g_coeff[b*TT1 + tp];
            if (tp < NT) {
                float4 h = *(const float4*)(enc + ((size_t)b*NT + tp)*ND + tid*4);
                acc.x = lw*h.x; acc.y = lw*h.y; acc.z = lw*h.z; acc.w = lw*h.w;
            }
            tstart = tp + 1;
        }
        for (int t = tstart; t <= te; ++t) {
            if (t >= NT) break;
            float cf = g_coeff[b*TT1 + t];
            float4 h = *(const float4*)(enc + ((size_t)b*NT + t)*ND + tid*4);
            acc.x = fmaf(cf, h.x, acc.x);
            acc.y = fmaf(cf, h.y, acc.y);
            acc.z = fmaf(cf, h.z, acc.z);
            acc.w = fmaf(cf, h.w, acc.w);
        }
    }
    *(float4*)(out + ((size_t)(b*TT1 + n))*ND + tid*4) = acc;
}

// ---------------- launch ----------------
extern "C" void kernel_launch(void* const* d_in, const int* in_sizes, int n_in,
                              void* d_out, int out_size) {
    (void)in_sizes; (void)n_in; (void)out_size;
    const float* enc  = (const float*)d_in[0];
    const float* mask = (const float*)d_in[1];
    const float* cw   = (const float*)d_in[2];
    const float* cb   = (const float*)d_in[3];
    const float* uw   = (const float*)d_in[4];
    const float* ub   = (const float*)d_in[5];
    const float* w1   = (const float*)d_in[6];
    const float* b1   = (const float*)d_in[7];
    const float* w2   = (const float*)d_in[8];
    const float* b2   = (const float*)d_in[9];
    float* out = (float*)d_out;

    cudaFuncSetAttribute(k_conv_gemm, cudaFuncAttributeMaxDynamicSharedMemorySize, SMEM_CONV);

    k_prep_wt<<<(3*ND*ND + 255)/256, 256>>>(cw);
    k_prep_vc<<<ND + 1, 160>>>(uw, w2, ub, b2);

    dim3 g1(8, 4, NB);               // t-tiles x o-tiles x batch
    k_conv_gemm<<<g1, 256, SMEM_CONV>>>(enc, cb, w1);

    k_alpha<<<(NB*NT + 255)/256, 256>>>(mask, b1, out + OFF_AT);
    k_scan<<<NB, 32>>>(mask, out);

    dim3 g4(TT1, NB);
    k_gather<<<g4, 128>>>(enc, out);
}